// round 4
// baseline (speedup 1.0000x reference)
#include <cuda_runtime.h>
#include <math.h>

#define BATCH 256
#define CH    64
#define MDIM  4096
#define NT    256

#define S1    8
#define M1    (MDIM/S1)        // 512 samples per gram CTA
#define LDT   68               // transposed tile stride

#define LDC   65               // cov stride
#define LDW   65               // Wt stride (kernel2 smem)

#define S2    8
#define TM3   128              // apply m-tile
#define T3    (MDIM/(S2*TM3))  // 4 tiles per apply CTA
#define LDX   132              // x tile stride
#define SMEM3 ((CH*LDX + CH*CH + CH)*4)

__device__ float g_gram[(size_t)BATCH*S1*CH*CH];
__device__ float g_sums[BATCH*S1*CH];
__device__ float g_W[(size_t)BATCH*CH*CH];
__device__ float g_mu[BATCH*CH];

// =============== Kernel 1: partial Gram + partial sums ===============
__global__ __launch_bounds__(NT)
void gram_kernel(const float* __restrict__ x)
{
    __shared__ __align__(16) float xt[CH*LDT];   // transposed tile xt[m][ch]
    __shared__ float s_part[CH][4];

    const int b = blockIdx.x, s = blockIdx.y, tid = threadIdx.x;
    const float* xb = x + (size_t)b * CH * MDIM + s * M1;

    // triangular 4x4-block mapping (tid < 136)
    int bi = 0, bj = 0;
    { int t = tid, r = 0; while (r < 16 && t >= 16 - r) { t -= 16 - r; r++; } bi = r; bj = r + t; }

    const int lc = tid >> 2, lq = tid & 3;

    float acc[4][4] = {};
    float ssum = 0.f;

    for (int t = 0; t < M1 / 64; ++t) {
        const int m0 = t * 64;
        __syncthreads();
        // lane-interleaved float4 loads (full 32B sectors per warp transaction)
        const float4* src = (const float4*)(xb + (size_t)lc * MDIM + m0);
#pragma unroll
        for (int v = 0; v < 4; ++v) {
            float4 d = src[lq + v * 4];
            ssum += (d.x + d.y) + (d.z + d.w);
            int j = lq * 4 + v * 16;
            xt[(j + 0) * LDT + lc] = d.x;
            xt[(j + 1) * LDT + lc] = d.y;
            xt[(j + 2) * LDT + lc] = d.z;
            xt[(j + 3) * LDT + lc] = d.w;
        }
        __syncthreads();
        if (tid < 136) {
#pragma unroll 8
            for (int j = 0; j < 64; ++j) {
                float4 a = *(const float4*)&xt[j * LDT + 4 * bi];
                float4 c = *(const float4*)&xt[j * LDT + 4 * bj];
                acc[0][0] += a.x*c.x; acc[0][1] += a.x*c.y; acc[0][2] += a.x*c.z; acc[0][3] += a.x*c.w;
                acc[1][0] += a.y*c.x; acc[1][1] += a.y*c.y; acc[1][2] += a.y*c.z; acc[1][3] += a.y*c.w;
                acc[2][0] += a.z*c.x; acc[2][1] += a.z*c.y; acc[2][2] += a.z*c.z; acc[2][3] += a.z*c.w;
                acc[3][0] += a.w*c.x; acc[3][1] += a.w*c.y; acc[3][2] += a.w*c.z; acc[3][3] += a.w*c.w;
            }
        }
    }

    s_part[lc][lq] = ssum;
    __syncthreads();
    if (tid < CH) {
        float t0 = ((s_part[tid][0] + s_part[tid][1]) + s_part[tid][2]) + s_part[tid][3];
        g_sums[(b * S1 + s) * CH + tid] = t0;
    }
    if (tid < 136) {
        float* gg = g_gram + (size_t)(b * S1 + s) * CH * CH;
#pragma unroll
        for (int i = 0; i < 4; i++)
#pragma unroll
            for (int j = 0; j < 4; j++)
                gg[(4 * bi + i) * CH + 4 * bj + j] = acc[i][j];
    }
}

// =============== Kernel 2: reduce + shrinkage + Cholesky + inverse ===============
#define A_(i,j) covb[(63-(i))*LDC + (63-(j))]

__global__ __launch_bounds__(NT)
void chol_kernel()
{
    __shared__ float covb[CH*LDC];
    __shared__ float Wt[CH*LDW];     // Wt[d][r] = W[r][d]
    __shared__ float s_mu[CH];
    __shared__ float s_invd[CH];
    __shared__ float s_w[8][2];
    __shared__ float s_bc[2];

    const int b = blockIdx.x, tid = threadIdx.x;

    if (tid < CH) {
        float m = 0.f;
#pragma unroll
        for (int s = 0; s < S1; s++) m += g_sums[(b * S1 + s) * CH + tid];
        s_mu[tid] = m * (1.f / MDIM);
    }
    __syncthreads();

    for (int idx = tid; idx < CH * CH; idx += NT) {
        int i = idx >> 6, j = idx & 63;
        if (i <= j) {
            float g = 0.f;
#pragma unroll
            for (int s = 0; s < S1; s++) g += g_gram[(size_t)(b * S1 + s) * CH * CH + idx];
            float v = g * (1.f / MDIM) - s_mu[i] * s_mu[j];
            covb[i * LDC + j] = v;
            covb[j * LDC + i] = v;
        }
    }
    __syncthreads();

    // trace / Frobenius^2 (deterministic)
    float tr_p = 0.f, fr_p = 0.f;
    for (int idx = tid; idx < CH * CH; idx += NT) {
        int i = idx >> 6, j = idx & 63;
        float v = covb[i * LDC + j];
        fr_p += v * v;
        if (i == j) tr_p += v;
    }
#pragma unroll
    for (int o = 16; o; o >>= 1) {
        tr_p += __shfl_down_sync(0xffffffffu, tr_p, o);
        fr_p += __shfl_down_sync(0xffffffffu, fr_p, o);
    }
    if ((tid & 31) == 0) { s_w[tid >> 5][0] = tr_p; s_w[tid >> 5][1] = fr_p; }
    __syncthreads();
    if (tid == 0) {
        float tr = 0.f, st = 0.f;
#pragma unroll
        for (int w = 0; w < 8; w++) { tr += s_w[w][0]; st += s_w[w][1]; }
        const float n = (float)MDIM, p = (float)CH;
        float num = (n - 2.f) / n * st + tr * tr;
        float den = (n + 2.f) * (st - tr * tr / p);
        float rho = fminf(num / den, 1.f);
        s_bc[0] = rho;
        s_bc[1] = rho * tr / p;
    }
    __syncthreads();
    {
        const float rho = s_bc[0], dadd = s_bc[1];
        for (int idx = tid; idx < CH * CH; idx += NT) {
            int i = idx >> 6, j = idx & 63;
            float v = covb[i * LDC + j] * (1.f - rho);
            if (i == j) v += dadd;
            covb[i * LDC + j] = v;
        }
    }

    // flipped Cholesky -> U (upper, cov = U U^T) in natural indexing
    for (int k = 0; k < CH; ++k) {
        __syncthreads();
        if (tid == 0) {
            float d = A_(k, k);
            float sd = sqrtf(d);
            A_(k, k) = sd;
            s_bc[0] = 1.f / sd;
        }
        __syncthreads();
        if (tid > k && tid < CH) A_(tid, k) *= s_bc[0];
        __syncthreads();
        {
            int ii = tid & 63, g = tid >> 6;
            int i = k + 1 + ii;
            if (i < CH) {
                float aik = A_(i, k);
                for (int j = k + 1 + g; j <= i; j += 4)
                    A_(i, j) -= aik * A_(j, k);
            }
        }
    }
    __syncthreads();

    if (tid < CH) s_invd[tid] = 1.f / covb[tid * LDC + tid];
    for (int idx = tid; idx < CH * LDW; idx += NT) Wt[idx] = 0.f;
    __syncthreads();

    // W = U^{-1}: thread j computes column j, stores Wt[j][i] = W[i][j]
    if (tid < CH) {
        const int j = tid;
        Wt[j * LDW + j] = s_invd[j];
        for (int i = j - 1; i >= 0; --i) {
            float a = 0.f;
            for (int k = i + 1; k <= j; ++k)
                a += covb[i * LDC + k] * Wt[j * LDW + k];
            Wt[j * LDW + i] = -a * s_invd[i];
        }
    }
    __syncthreads();

    for (int idx = tid; idx < CH * CH; idx += NT) {
        int d = idx >> 6, r = idx & 63;
        g_W[(size_t)b * CH * CH + idx] = Wt[d * LDW + r];
    }
    if (tid < CH) g_mu[b * CH + tid] = s_mu[tid];
}

// =============== Kernel 3: Z = W (x - mu) ===============
extern __shared__ float smem3[];

__global__ __launch_bounds__(NT)
void apply_kernel(const float* __restrict__ x, float* __restrict__ z)
{
    float* xs = smem3;                 // [CH][LDX]
    float* Ws = smem3 + CH * LDX;      // [CH][CH], Ws[d][r] = W[r][d]
    float* mu = Ws + CH * CH;

    const int b = blockIdx.x, s = blockIdx.y, tid = threadIdx.x;
    const float* xb = x + (size_t)b * CH * MDIM;
    float*       zb = z + (size_t)b * CH * MDIM;

    {
        const float4* src = (const float4*)(g_W + (size_t)b * CH * CH);
        float4* dst = (float4*)Ws;
        for (int i = tid; i < CH * CH / 4; i += NT) dst[i] = src[i];
    }
    if (tid < CH) mu[tid] = g_mu[b * CH + tid];

    const int lc = tid >> 2, lq = tid & 3;
    const int ty = tid >> 5, tx = tid & 31;
    const int r0 = 8 * ty, c0 = 4 * tx;
    __syncthreads();
    const float mu_c = mu[lc];

    for (int t = 0; t < T3; ++t) {
        const int m0 = s * (T3 * TM3) + t * TM3;
        if (t) __syncthreads();
        // load 64x128 tile, subtract mu; lane-interleaved float4
        const float4* src = (const float4*)(xb + (size_t)lc * MDIM + m0);
        {
#pragma unroll
            for (int v = 0; v < 8; ++v) {
                float4 d = src[lq + v * 4];
                d.x -= mu_c; d.y -= mu_c; d.z -= mu_c; d.w -= mu_c;
                *(float4*)&xs[lc * LDX + lq * 4 + v * 16] = d;
            }
        }
        __syncthreads();

        float4 zz[8] = {};
#pragma unroll 4
        for (int d = r0; d < CH; ++d) {
            float4 w0 = *(const float4*)&Ws[d * CH + r0];       // warp-uniform broadcast
            float4 w1 = *(const float4*)&Ws[d * CH + r0 + 4];
            float4 xv = *(const float4*)&xs[d * LDX + c0];
            zz[0].x += w0.x*xv.x; zz[0].y += w0.x*xv.y; zz[0].z += w0.x*xv.z; zz[0].w += w0.x*xv.w;
            zz[1].x += w0.y*xv.x; zz[1].y += w0.y*xv.y; zz[1].z += w0.y*xv.z; zz[1].w += w0.y*xv.w;
            zz[2].x += w0.z*xv.x; zz[2].y += w0.z*xv.y; zz[2].z += w0.z*xv.z; zz[2].w += w0.z*xv.w;
            zz[3].x += w0.w*xv.x; zz[3].y += w0.w*xv.y; zz[3].z += w0.w*xv.z; zz[3].w += w0.w*xv.w;
            zz[4].x += w1.x*xv.x; zz[4].y += w1.x*xv.y; zz[4].z += w1.x*xv.z; zz[4].w += w1.x*xv.w;
            zz[5].x += w1.y*xv.x; zz[5].y += w1.y*xv.y; zz[5].z += w1.y*xv.z; zz[5].w += w1.y*xv.w;
            zz[6].x += w1.z*xv.x; zz[6].y += w1.z*xv.y; zz[6].z += w1.z*xv.z; zz[6].w += w1.z*xv.w;
            zz[7].x += w1.w*xv.x; zz[7].y += w1.w*xv.y; zz[7].z += w1.w*xv.z; zz[7].w += w1.w*xv.w;
        }
#pragma unroll
        for (int r = 0; r < 8; ++r)
            *(float4*)(zb + (size_t)(r0 + r) * MDIM + m0 + c0) = zz[r];
    }
}

extern "C" void kernel_launch(void* const* d_in, const int* in_sizes, int n_in,
                              void* d_out, int out_size)
{
    const float* x = (const float*)d_in[0];
    float* z = (float*)d_out;

    cudaFuncSetAttribute(apply_kernel, cudaFuncAttributeMaxDynamicSharedMemorySize, SMEM3);

    gram_kernel<<<dim3(BATCH, S1), NT>>>(x);
    chol_kernel<<<BATCH, NT>>>();
    apply_kernel<<<dim3(BATCH, S2), NT, SMEM3>>>(x, z);
}

// round 6
// speedup vs baseline: 1.3086x; 1.3086x over previous
#include <cuda_runtime.h>
#include <cuda_bf16.h>
#include <cstdint>
#include <math.h>

#define BATCH 256
#define CH    64
#define MDIM  4096
#define NT    256
#define S1G   4
#define T1G   ((MDIM/S1G)/64)   // 16 tiles per gram CTA
#define S2A   8
#define T2A   ((MDIM/S2A)/64)   // 8 tiles per apply CTA
#define LDB   72                // bf16 elements per smem row
#define RB    144               // row bytes
#define LDC   65
#define LDW   65

__device__ float g_gram[(size_t)BATCH*S1G*CH*CH];
__device__ float g_sums[BATCH*S1G*CH];
__device__ float g_W[(size_t)BATCH*CH*CH];
__device__ float g_mu[BATCH*CH];

__device__ __forceinline__ uint32_t smem_u32(const void* p) {
    uint32_t a;
    asm("{ .reg .u64 t; cvta.to.shared.u64 t, %1; cvt.u32.u64 %0, t; }" : "=r"(a) : "l"(p));
    return a;
}
#define STS64V2(a,r0,r1) asm volatile("st.shared.v2.b32 [%0], {%1,%2};" :: "r"(a), "r"(r0), "r"(r1) : "memory")
#define CVT_BF2(res,flo,fhi) asm("cvt.rn.satfinite.bf16x2.f32 %0, %1, %2;" : "=r"(res) : "f"(fhi), "f"(flo))

__device__ __forceinline__ void split_pair(float f0, float f1, uint32_t& uh, uint32_t& ul) {
    CVT_BF2(uh, f0, f1);
    float h0 = __uint_as_float(uh << 16);
    float h1 = __uint_as_float(uh & 0xffff0000u);
    CVT_BF2(ul, f0 - h0, f1 - h1);
}
__device__ __forceinline__ void ldm_x4(uint32_t* r, uint32_t addr) {
    asm volatile("ldmatrix.sync.aligned.m8n8.x4.shared.b16 {%0,%1,%2,%3}, [%4];"
                 : "=r"(r[0]), "=r"(r[1]), "=r"(r[2]), "=r"(r[3]) : "r"(addr));
}
__device__ __forceinline__ void ldm_x4t(uint32_t* r, uint32_t addr) {
    asm volatile("ldmatrix.sync.aligned.m8n8.x4.trans.shared.b16 {%0,%1,%2,%3}, [%4];"
                 : "=r"(r[0]), "=r"(r[1]), "=r"(r[2]), "=r"(r[3]) : "r"(addr));
}
__device__ __forceinline__ void mma16816(float* d, const uint32_t* a, uint32_t b0, uint32_t b1) {
    asm volatile("mma.sync.aligned.m16n8k16.row.col.f32.bf16.bf16.f32 "
                 "{%0,%1,%2,%3}, {%4,%5,%6,%7}, {%8,%9}, {%0,%1,%2,%3};"
                 : "+f"(d[0]), "+f"(d[1]), "+f"(d[2]), "+f"(d[3])
                 : "r"(a[0]), "r"(a[1]), "r"(a[2]), "r"(a[3]), "r"(b0), "r"(b1));
}

// =============== Kernel 1: partial Gram via HMMA bf16 split ===============
__global__ __launch_bounds__(NT)
void gram_kernel(const float* __restrict__ x)
{
    __shared__ __align__(16) __nv_bfloat16 sh[CH*LDB];
    __shared__ __align__(16) __nv_bfloat16 sl[CH*LDB];
    __shared__ float sp[NT];

    const int b = blockIdx.x, s = blockIdx.y, tid = threadIdx.x;
    const float* xb = x + (size_t)b * CH * MDIM + (size_t)s * (MDIM / S1G);
    const uint32_t hb = smem_u32(sh), lb = smem_u32(sl);

    const int c = tid >> 2, q = tid & 3;
    const int w = tid >> 5, lane = tid & 31;
    const int r0 = (w >> 1) * 16, c0 = (w & 1) * 32;
    const int grp = lane >> 3, li = lane & 7;

    const uint32_t aoff = (uint32_t)(r0 + li + (grp & 1) * 8) * RB + (uint32_t)((grp >> 1) * 8) * 2;
    const uint32_t boff = (uint32_t)(c0 + li + (grp >> 1) * 8) * RB + (uint32_t)((grp & 1) * 8) * 2;

    float D[4][4] = {};
    float ssum = 0.f;

    for (int t = 0; t < T1G; ++t) {
        if (t) __syncthreads();
        const float4* src = (const float4*)(xb + (size_t)c * MDIM + t * 64);
#pragma unroll
        for (int j = 0; j < 4; ++j) {
            float4 v = src[q + 4 * j];
            ssum += (v.x + v.y) + (v.z + v.w);
            uint32_t h0, l0, h1, l1;
            split_pair(v.x, v.y, h0, l0);
            split_pair(v.z, v.w, h1, l1);
            uint32_t off = (uint32_t)c * RB + (uint32_t)(q + 4 * j) * 8;
            STS64V2(hb + off, h0, h1);
            STS64V2(lb + off, l0, l1);
        }
        __syncthreads();
#pragma unroll
        for (int kc = 0; kc < 4; ++kc) {
            const uint32_t ka = (uint32_t)kc * 32;
            uint32_t ah[4], al[4], bh0[4], bh1[4], bl0[4], bl1[4];
            ldm_x4(ah, hb + aoff + ka);
            ldm_x4(al, lb + aoff + ka);
            ldm_x4(bh0, hb + boff + ka);
            ldm_x4(bh1, hb + boff + ka + 16 * RB);
            ldm_x4(bl0, lb + boff + ka);
            ldm_x4(bl1, lb + boff + ka + 16 * RB);
            mma16816(D[0], ah, bh0[0], bh0[1]);
            mma16816(D[0], ah, bl0[0], bl0[1]);
            mma16816(D[0], al, bh0[0], bh0[1]);
            mma16816(D[1], ah, bh0[2], bh0[3]);
            mma16816(D[1], ah, bl0[2], bl0[3]);
            mma16816(D[1], al, bh0[2], bh0[3]);
            mma16816(D[2], ah, bh1[0], bh1[1]);
            mma16816(D[2], ah, bl1[0], bl1[1]);
            mma16816(D[2], al, bh1[0], bh1[1]);
            mma16816(D[3], ah, bh1[2], bh1[3]);
            mma16816(D[3], ah, bl1[2], bl1[3]);
            mma16816(D[3], al, bh1[2], bh1[3]);
        }
    }

    sp[tid] = ssum;
    __syncthreads();
    if (tid < CH)
        g_sums[(b * S1G + s) * CH + tid] =
            ((sp[tid * 4] + sp[tid * 4 + 1]) + sp[tid * 4 + 2]) + sp[tid * 4 + 3];

    float* gg = g_gram + (size_t)(b * S1G + s) * CH * CH;
    const int row = r0 + (lane >> 2);
    const int col = c0 + (lane & 3) * 2;
#pragma unroll
    for (int nb = 0; nb < 4; ++nb) {
        *(float2*)(gg + (size_t)row * CH + col + nb * 8)       = make_float2(D[nb][0], D[nb][1]);
        *(float2*)(gg + (size_t)(row + 8) * CH + col + nb * 8) = make_float2(D[nb][2], D[nb][3]);
    }
}

// =============== Kernel 2: reduce + shrinkage + Cholesky + inverse ===============
#define A_(i,j) covb[(63-(i))*LDC + (63-(j))]

__global__ __launch_bounds__(NT)
void chol_kernel()
{
    __shared__ float covb[CH*LDC];
    __shared__ float Wt[CH*LDW];
    __shared__ float s_mu[CH];
    __shared__ float s_invd[CH];
    __shared__ float s_w[8][2];
    __shared__ float s_bc[2];

    const int b = blockIdx.x, tid = threadIdx.x;

    if (tid < CH) {
        float m = 0.f;
#pragma unroll
        for (int s = 0; s < S1G; s++) m += g_sums[(b * S1G + s) * CH + tid];
        s_mu[tid] = m * (1.f / MDIM);
    }
    __syncthreads();

    for (int idx = tid; idx < CH * CH; idx += NT) {
        int i = idx >> 6, j = idx & 63;
        if (i <= j) {
            float g = 0.f;
#pragma unroll
            for (int p = 0; p < S1G; p++)
                g += g_gram[((size_t)(b * S1G + p)) * (CH * CH) + idx];
            float v = g * (1.f / MDIM) - s_mu[i] * s_mu[j];
            covb[i * LDC + j] = v;
            covb[j * LDC + i] = v;
        }
    }
    __syncthreads();

    float tr_p = 0.f, fr_p = 0.f;
    for (int idx = tid; idx < CH * CH; idx += NT) {
        int i = idx >> 6, j = idx & 63;
        float v = covb[i * LDC + j];
        fr_p += v * v;
        if (i == j) tr_p += v;
    }
#pragma unroll
    for (int o = 16; o; o >>= 1) {
        tr_p += __shfl_down_sync(0xffffffffu, tr_p, o);
        fr_p += __shfl_down_sync(0xffffffffu, fr_p, o);
    }
    if ((tid & 31) == 0) { s_w[tid >> 5][0] = tr_p; s_w[tid >> 5][1] = fr_p; }
    __syncthreads();
    if (tid == 0) {
        float tr = 0.f, st = 0.f;
#pragma unroll
        for (int w = 0; w < 8; w++) { tr += s_w[w][0]; st += s_w[w][1]; }
        const float n = (float)MDIM, p = (float)CH;
        float num = (n - 2.f) / n * st + tr * tr;
        float den = (n + 2.f) * (st - tr * tr / p);
        float rho = fminf(num / den, 1.f);
        s_bc[0] = rho;
        s_bc[1] = rho * tr / p;
    }
    __syncthreads();
    {
        const float rho = s_bc[0], dadd = s_bc[1];
        for (int idx = tid; idx < CH * CH; idx += NT) {
            int i = idx >> 6, j = idx & 63;
            float v = covb[i * LDC + j] * (1.f - rho);
            if (i == j) v += dadd;
            covb[i * LDC + j] = v;
        }
    }

    for (int k = 0; k < CH; ++k) {
        __syncthreads();
        if (tid == 0) {
            float d = A_(k, k);
            float sd = sqrtf(d);
            A_(k, k) = sd;
            s_bc[0] = 1.f / sd;
        }
        __syncthreads();
        if (tid > k && tid < CH) A_(tid, k) *= s_bc[0];
        __syncthreads();
        {
            int ii = tid & 63, g = tid >> 6;
            int i = k + 1 + ii;
            if (i < CH) {
                float aik = A_(i, k);
                for (int j = k + 1 + g; j <= i; j += 4)
                    A_(i, j) -= aik * A_(j, k);
            }
        }
    }
    __syncthreads();

    if (tid < CH) s_invd[tid] = 1.f / covb[tid * LDC + tid];
    for (int idx = tid; idx < CH * LDW; idx += NT) Wt[idx] = 0.f;
    __syncthreads();

    if (tid < CH) {
        const int j = tid;
        Wt[j * LDW + j] = s_invd[j];
        for (int i = j - 1; i >= 0; --i) {
            float a = 0.f;
            for (int k = i + 1; k <= j; ++k)
                a += covb[i * LDC + k] * Wt[j * LDW + k];
            Wt[j * LDW + i] = -a * s_invd[i];
        }
    }
    __syncthreads();

    // store W row-major: g_W[c][d] = W[c][d] = Wt[d][c]
    for (int idx = tid; idx < CH * CH; idx += NT) {
        int cc = idx >> 6, d = idx & 63;
        g_W[(size_t)b * CH * CH + idx] = Wt[d * LDW + cc];
    }
    if (tid < CH) g_mu[b * CH + tid] = s_mu[tid];
}

// =============== Kernel 3: Z = W (x - mu) via HMMA bf16 split ===============
__global__ __launch_bounds__(NT)
void apply_kernel(const float* __restrict__ x, float* __restrict__ z)
{
    __shared__ __align__(16) __nv_bfloat16 wh[CH*LDB];
    __shared__ __align__(16) __nv_bfloat16 wl[CH*LDB];
    __shared__ __align__(16) __nv_bfloat16 xh[CH*LDB];
    __shared__ __align__(16) __nv_bfloat16 xl[CH*LDB];

    const int b = blockIdx.x, s = blockIdx.y, tid = threadIdx.x;
    const float* xb = x + (size_t)b * CH * MDIM;
    float*       zb = z + (size_t)b * CH * MDIM;
    const uint32_t whb = smem_u32(wh), wlb = smem_u32(wl);
    const uint32_t xhb = smem_u32(xh), xlb = smem_u32(xl);

    const int c = tid >> 2, q = tid & 3;
    const int w = tid >> 5, lane = tid & 31;
    const int r0 = (w >> 1) * 16, m0 = (w & 1) * 32;
    const int grp = lane >> 3, li = lane & 7;

    const float mu_c = g_mu[b * CH + c];

    // load + split W (row-major [c][d])
    {
        const float4* wsrc = (const float4*)(g_W + (size_t)b * CH * CH + (size_t)c * CH);
#pragma unroll
        for (int j = 0; j < 4; ++j) {
            float4 v = wsrc[q + 4 * j];
            uint32_t h0, l0, h1, l1;
            split_pair(v.x, v.y, h0, l0);
            split_pair(v.z, v.w, h1, l1);
            uint32_t off = (uint32_t)c * RB + (uint32_t)(q + 4 * j) * 8;
            STS64V2(whb + off, h0, h1);
            STS64V2(wlb + off, l0, l1);
        }
    }
    __syncthreads();

    // preload W fragments (reused for all tiles)
    uint32_t wah[4][4], wal[4][4];
    {
        const uint32_t aoff = (uint32_t)(r0 + li + (grp & 1) * 8) * RB + (uint32_t)((grp >> 1) * 8) * 2;
#pragma unroll
        for (int kc = 0; kc < 4; ++kc) {
            ldm_x4(wah[kc], whb + aoff + kc * 32);
            ldm_x4(wal[kc], wlb + aoff + kc * 32);
        }
    }

    const uint32_t boff = (uint32_t)(li + (grp & 1) * 8) * RB + (uint32_t)(m0 + (grp >> 1) * 8) * 2;

    for (int t = 0; t < T2A; ++t) {
        if (t) __syncthreads();
        const int mg0 = s * (T2A * 64) + t * 64;
        const float4* src = (const float4*)(xb + (size_t)c * MDIM + mg0);
#pragma unroll
        for (int j = 0; j < 4; ++j) {
            float4 v = src[q + 4 * j];
            v.x -= mu_c; v.y -= mu_c; v.z -= mu_c; v.w -= mu_c;
            uint32_t h0, l0, h1, l1;
            split_pair(v.x, v.y, h0, l0);
            split_pair(v.z, v.w, h1, l1);
            uint32_t off = (uint32_t)c * RB + (uint32_t)(q + 4 * j) * 8;
            STS64V2(xhb + off, h0, h1);
            STS64V2(xlb + off, l0, l1);
        }
        __syncthreads();

        float D[4][4] = {};
#pragma unroll
        for (int kc = 0; kc < 4; ++kc) {
            const uint32_t kb = (uint32_t)(kc * 16) * RB;
            uint32_t bh0[4], bh1[4], bl0[4], bl1[4];
            ldm_x4t(bh0, xhb + boff + kb);
            ldm_x4t(bh1, xhb + boff + kb + 32);
            ldm_x4t(bl0, xlb + boff + kb);
            ldm_x4t(bl1, xlb + boff + kb + 32);
            mma16816(D[0], wah[kc], bh0[0], bh0[1]);
            mma16816(D[0], wah[kc], bl0[0], bl0[1]);
            mma16816(D[0], wal[kc], bh0[0], bh0[1]);
            mma16816(D[1], wah[kc], bh0[2], bh0[3]);
            mma16816(D[1], wah[kc], bl0[2], bl0[3]);
            mma16816(D[1], wal[kc], bh0[2], bh0[3]);
            mma16816(D[2], wah[kc], bh1[0], bh1[1]);
            mma16816(D[2], wah[kc], bl1[0], bl1[1]);
            mma16816(D[2], wal[kc], bh1[0], bh1[1]);
            mma16816(D[3], wah[kc], bh1[2], bh1[3]);
            mma16816(D[3], wah[kc], bl1[2], bl1[3]);
            mma16816(D[3], wal[kc], bh1[2], bh1[3]);
        }

        const int row = r0 + (lane >> 2);
        const int mg = mg0 + m0 + (lane & 3) * 2;
#pragma unroll
        for (int nb = 0; nb < 4; ++nb) {
            *(float2*)(zb + (size_t)row * MDIM + mg + nb * 8)       = make_float2(D[nb][0], D[nb][1]);
            *(float2*)(zb + (size_t)(row + 8) * MDIM + mg + nb * 8) = make_float2(D[nb][2], D[nb][3]);
        }
    }
}

extern "C" void kernel_launch(void* const* d_in, const int* in_sizes, int n_in,
                              void* d_out, int out_size)
{
    const float* x = (const float*)d_in[0];
    float* z = (float*)d_out;

    gram_kernel<<<dim3(BATCH, S1G), NT>>>(x);
    chol_kernel<<<BATCH, NT>>>();
    apply_kernel<<<dim3(BATCH, S2A), NT>>>(x, z);
}

// round 7
// speedup vs baseline: 1.4697x; 1.1231x over previous
#include <cuda_runtime.h>
#include <cuda_bf16.h>
#include <cstdint>
#include <math.h>

#define BATCH 256
#define CH    64
#define MDIM  4096
#define NT    256
#define S1G   4
#define T1G   ((MDIM/S1G)/64)   // 16 tiles per gram CTA
#define S2A   8
#define T2A   ((MDIM/S2A)/64)   // 8 tiles per apply CTA
#define LDB   72                // bf16 elements per smem row
#define RB    144               // row bytes
#define LDC   65
#define LDW   65

__device__ float g_gram[(size_t)BATCH*S1G*CH*CH];
__device__ float g_sums[BATCH*S1G*CH];
__device__ float g_W[(size_t)BATCH*CH*CH];
__device__ float g_mu[BATCH*CH];

__device__ __forceinline__ uint32_t smem_u32(const void* p) {
    uint32_t a;
    asm("{ .reg .u64 t; cvta.to.shared.u64 t, %1; cvt.u32.u64 %0, t; }" : "=r"(a) : "l"(p));
    return a;
}
#define STS64V2(a,r0,r1) asm volatile("st.shared.v2.b32 [%0], {%1,%2};" :: "r"(a), "r"(r0), "r"(r1) : "memory")
#define CVT_BF2(res,flo,fhi) asm("cvt.rn.satfinite.bf16x2.f32 %0, %1, %2;" : "=r"(res) : "f"(fhi), "f"(flo))

__device__ __forceinline__ void split_pair(float f0, float f1, uint32_t& uh, uint32_t& ul) {
    CVT_BF2(uh, f0, f1);
    float h0 = __uint_as_float(uh << 16);
    float h1 = __uint_as_float(uh & 0xffff0000u);
    CVT_BF2(ul, f0 - h0, f1 - h1);
}
__device__ __forceinline__ void ldm_x4(uint32_t* r, uint32_t addr) {
    asm volatile("ldmatrix.sync.aligned.m8n8.x4.shared.b16 {%0,%1,%2,%3}, [%4];"
                 : "=r"(r[0]), "=r"(r[1]), "=r"(r[2]), "=r"(r[3]) : "r"(addr));
}
__device__ __forceinline__ void ldm_x4t(uint32_t* r, uint32_t addr) {
    asm volatile("ldmatrix.sync.aligned.m8n8.x4.trans.shared.b16 {%0,%1,%2,%3}, [%4];"
                 : "=r"(r[0]), "=r"(r[1]), "=r"(r[2]), "=r"(r[3]) : "r"(addr));
}
__device__ __forceinline__ void mma16816(float* d, const uint32_t* a, uint32_t b0, uint32_t b1) {
    asm volatile("mma.sync.aligned.m16n8k16.row.col.f32.bf16.bf16.f32 "
                 "{%0,%1,%2,%3}, {%4,%5,%6,%7}, {%8,%9}, {%0,%1,%2,%3};"
                 : "+f"(d[0]), "+f"(d[1]), "+f"(d[2]), "+f"(d[3])
                 : "r"(a[0]), "r"(a[1]), "r"(a[2]), "r"(a[3]), "r"(b0), "r"(b1));
}

// =============== Kernel 1: partial Gram via HMMA bf16 split (pipelined) ===============
__global__ __launch_bounds__(NT)
void gram_kernel(const float* __restrict__ x)
{
    __shared__ __align__(16) __nv_bfloat16 sh[CH*LDB];
    __shared__ __align__(16) __nv_bfloat16 sl[CH*LDB];
    __shared__ float sp[NT];

    const int b = blockIdx.x, s = blockIdx.y, tid = threadIdx.x;
    const float* xb = x + (size_t)b * CH * MDIM + (size_t)s * (MDIM / S1G);
    const uint32_t hb = smem_u32(sh), lb = smem_u32(sl);

    const int c = tid >> 2, q = tid & 3;
    const int w = tid >> 5, lane = tid & 31;
    const int r0 = (w >> 1) * 16, c0 = (w & 1) * 32;
    const int grp = lane >> 3, li = lane & 7;

    const uint32_t aoff = (uint32_t)(r0 + li + (grp & 1) * 8) * RB + (uint32_t)((grp >> 1) * 8) * 2;
    const uint32_t boff = (uint32_t)(c0 + li + (grp >> 1) * 8) * RB + (uint32_t)((grp & 1) * 8) * 2;

    float D[4][4] = {};
    float ssum = 0.f;

    float4 stage[4];
    {
        const float4* src = (const float4*)(xb + (size_t)c * MDIM);
#pragma unroll
        for (int j = 0; j < 4; ++j) stage[j] = src[q + 4 * j];
    }

    for (int t = 0; t < T1G; ++t) {
        // convert + store staged tile
#pragma unroll
        for (int j = 0; j < 4; ++j) {
            float4 v = stage[j];
            ssum += (v.x + v.y) + (v.z + v.w);
            uint32_t h0, l0, h1, l1;
            split_pair(v.x, v.y, h0, l0);
            split_pair(v.z, v.w, h1, l1);
            uint32_t off = (uint32_t)c * RB + (uint32_t)(q + 4 * j) * 8;
            STS64V2(hb + off, h0, h1);
            STS64V2(lb + off, l0, l1);
        }
        __syncthreads();

        // prefetch next tile (LDG latency overlaps MMA block below)
        if (t + 1 < T1G) {
            const float4* src = (const float4*)(xb + (size_t)c * MDIM + (t + 1) * 64);
#pragma unroll
            for (int j = 0; j < 4; ++j) stage[j] = src[q + 4 * j];
        }

#pragma unroll
        for (int kc = 0; kc < 4; ++kc) {
            const uint32_t ka = (uint32_t)kc * 32;
            uint32_t ah[4], al[4], bh0[4], bh1[4], bl0[4], bl1[4];
            ldm_x4(ah, hb + aoff + ka);
            ldm_x4(al, lb + aoff + ka);
            ldm_x4(bh0, hb + boff + ka);
            ldm_x4(bh1, hb + boff + ka + 16 * RB);
            ldm_x4(bl0, lb + boff + ka);
            ldm_x4(bl1, lb + boff + ka + 16 * RB);
            mma16816(D[0], ah, bh0[0], bh0[1]);
            mma16816(D[0], ah, bl0[0], bl0[1]);
            mma16816(D[0], al, bh0[0], bh0[1]);
            mma16816(D[1], ah, bh0[2], bh0[3]);
            mma16816(D[1], ah, bl0[2], bl0[3]);
            mma16816(D[1], al, bh0[2], bh0[3]);
            mma16816(D[2], ah, bh1[0], bh1[1]);
            mma16816(D[2], ah, bl1[0], bl1[1]);
            mma16816(D[2], al, bh1[0], bh1[1]);
            mma16816(D[3], ah, bh1[2], bh1[3]);
            mma16816(D[3], ah, bl1[2], bl1[3]);
            mma16816(D[3], al, bh1[2], bh1[3]);
        }
        __syncthreads();
    }

    sp[tid] = ssum;
    __syncthreads();
    if (tid < CH)
        g_sums[(b * S1G + s) * CH + tid] =
            ((sp[tid * 4] + sp[tid * 4 + 1]) + sp[tid * 4 + 2]) + sp[tid * 4 + 3];

    float* gg = g_gram + (size_t)(b * S1G + s) * CH * CH;
    const int row = r0 + (lane >> 2);
    const int col = c0 + (lane & 3) * 2;
#pragma unroll
    for (int nb = 0; nb < 4; ++nb) {
        *(float2*)(gg + (size_t)row * CH + col + nb * 8)       = make_float2(D[nb][0], D[nb][1]);
        *(float2*)(gg + (size_t)(row + 8) * CH + col + nb * 8) = make_float2(D[nb][2], D[nb][3]);
    }
}

// =============== Kernel 2: reduce + shrinkage + Cholesky + inverse ===============
#define A_(i,j) covb[(63-(i))*LDC + (63-(j))]

__global__ __launch_bounds__(NT)
void chol_kernel()
{
    __shared__ float covb[CH*LDC];
    __shared__ float Wt[CH*LDW];
    __shared__ float s_mu[CH];
    __shared__ float s_invd[CH];
    __shared__ float s_w[8][2];
    __shared__ float s_bc[2];

    const int b = blockIdx.x, tid = threadIdx.x;

    if (tid < CH) {
        float m = 0.f;
#pragma unroll
        for (int s = 0; s < S1G; s++) m += g_sums[(b * S1G + s) * CH + tid];
        s_mu[tid] = m * (1.f / MDIM);
    }
    __syncthreads();

    for (int idx = tid; idx < CH * CH; idx += NT) {
        int i = idx >> 6, j = idx & 63;
        if (i <= j) {
            float g = 0.f;
#pragma unroll
            for (int p = 0; p < S1G; p++)
                g += g_gram[((size_t)(b * S1G + p)) * (CH * CH) + idx];
            float v = g * (1.f / MDIM) - s_mu[i] * s_mu[j];
            covb[i * LDC + j] = v;
            covb[j * LDC + i] = v;
        }
    }
    __syncthreads();

    float tr_p = 0.f, fr_p = 0.f;
    for (int idx = tid; idx < CH * CH; idx += NT) {
        int i = idx >> 6, j = idx & 63;
        float v = covb[i * LDC + j];
        fr_p += v * v;
        if (i == j) tr_p += v;
    }
#pragma unroll
    for (int o = 16; o; o >>= 1) {
        tr_p += __shfl_down_sync(0xffffffffu, tr_p, o);
        fr_p += __shfl_down_sync(0xffffffffu, fr_p, o);
    }
    if ((tid & 31) == 0) { s_w[tid >> 5][0] = tr_p; s_w[tid >> 5][1] = fr_p; }
    __syncthreads();
    if (tid == 0) {
        float tr = 0.f, st = 0.f;
#pragma unroll
        for (int w = 0; w < 8; w++) { tr += s_w[w][0]; st += s_w[w][1]; }
        const float n = (float)MDIM, p = (float)CH;
        float num = (n - 2.f) / n * st + tr * tr;
        float den = (n + 2.f) * (st - tr * tr / p);
        float rho = fminf(num / den, 1.f);
        s_bc[0] = rho;
        s_bc[1] = rho * tr / p;
    }
    __syncthreads();
    {
        const float rho = s_bc[0], dadd = s_bc[1];
        for (int idx = tid; idx < CH * CH; idx += NT) {
            int i = idx >> 6, j = idx & 63;
            float v = covb[i * LDC + j] * (1.f - rho);
            if (i == j) v += dadd;
            covb[i * LDC + j] = v;
        }
    }

    for (int k = 0; k < CH; ++k) {
        __syncthreads();
        if (tid == 0) {
            float d = A_(k, k);
            float sd = sqrtf(d);
            A_(k, k) = sd;
            s_bc[0] = 1.f / sd;
        }
        __syncthreads();
        if (tid > k && tid < CH) A_(tid, k) *= s_bc[0];
        __syncthreads();
        {
            int ii = tid & 63, g = tid >> 6;
            int i = k + 1 + ii;
            if (i < CH) {
                float aik = A_(i, k);
                for (int j = k + 1 + g; j <= i; j += 4)
                    A_(i, j) -= aik * A_(j, k);
            }
        }
    }
    __syncthreads();

    if (tid < CH) s_invd[tid] = 1.f / covb[tid * LDC + tid];
    for (int idx = tid; idx < CH * LDW; idx += NT) Wt[idx] = 0.f;
    __syncthreads();

    if (tid < CH) {
        const int j = tid;
        Wt[j * LDW + j] = s_invd[j];
        for (int i = j - 1; i >= 0; --i) {
            float a = 0.f;
            for (int k = i + 1; k <= j; ++k)
                a += covb[i * LDC + k] * Wt[j * LDW + k];
            Wt[j * LDW + i] = -a * s_invd[i];
        }
    }
    __syncthreads();

    // store W row-major: g_W[c][d] = W[c][d] = Wt[d][c]
    for (int idx = tid; idx < CH * CH; idx += NT) {
        int cc = idx >> 6, d = idx & 63;
        g_W[(size_t)b * CH * CH + idx] = Wt[d * LDW + cc];
    }
    if (tid < CH) g_mu[b * CH + tid] = s_mu[tid];
}

// =============== Kernel 3: Z = W (x - mu) via HMMA bf16 split (pipelined) ===============
__global__ __launch_bounds__(NT)
void apply_kernel(const float* __restrict__ x, float* __restrict__ z)
{
    __shared__ __align__(16) __nv_bfloat16 wh[CH*LDB];
    __shared__ __align__(16) __nv_bfloat16 wl[CH*LDB];
    __shared__ __align__(16) __nv_bfloat16 xh[CH*LDB];
    __shared__ __align__(16) __nv_bfloat16 xl[CH*LDB];

    const int b = blockIdx.x, s = blockIdx.y, tid = threadIdx.x;
    const float* xb = x + (size_t)b * CH * MDIM;
    float*       zb = z + (size_t)b * CH * MDIM;
    const uint32_t whb = smem_u32(wh), wlb = smem_u32(wl);
    const uint32_t xhb = smem_u32(xh), xlb = smem_u32(xl);

    const int c = tid >> 2, q = tid & 3;
    const int w = tid >> 5, lane = tid & 31;
    const int r0 = (w >> 1) * 16, m0 = (w & 1) * 32;
    const int grp = lane >> 3, li = lane & 7;

    const float mu_c = g_mu[b * CH + c];

    // load + split W (row-major [c][d])
    {
        const float4* wsrc = (const float4*)(g_W + (size_t)b * CH * CH + (size_t)c * CH);
#pragma unroll
        for (int j = 0; j < 4; ++j) {
            float4 v = wsrc[q + 4 * j];
            uint32_t h0, l0, h1, l1;
            split_pair(v.x, v.y, h0, l0);
            split_pair(v.z, v.w, h1, l1);
            uint32_t off = (uint32_t)c * RB + (uint32_t)(q + 4 * j) * 8;
            STS64V2(whb + off, h0, h1);
            STS64V2(wlb + off, l0, l1);
        }
    }

    // prefetch first x tile while W settles
    float4 stage[4];
    {
        const float4* src = (const float4*)(xb + (size_t)c * MDIM + s * (T2A * 64));
#pragma unroll
        for (int j = 0; j < 4; ++j) stage[j] = src[q + 4 * j];
    }
    __syncthreads();

    // preload W fragments (reused for all tiles)
    uint32_t wah[4][4], wal[4][4];
    {
        const uint32_t aoff = (uint32_t)(r0 + li + (grp & 1) * 8) * RB + (uint32_t)((grp >> 1) * 8) * 2;
#pragma unroll
        for (int kc = 0; kc < 4; ++kc) {
            ldm_x4(wah[kc], whb + aoff + kc * 32);
            ldm_x4(wal[kc], wlb + aoff + kc * 32);
        }
    }

    const uint32_t boff = (uint32_t)(li + (grp & 1) * 8) * RB + (uint32_t)(m0 + (grp >> 1) * 8) * 2;

    for (int t = 0; t < T2A; ++t) {
        const int mg0 = s * (T2A * 64) + t * 64;
#pragma unroll
        for (int j = 0; j < 4; ++j) {
            float4 v = stage[j];
            v.x -= mu_c; v.y -= mu_c; v.z -= mu_c; v.w -= mu_c;
            uint32_t h0, l0, h1, l1;
            split_pair(v.x, v.y, h0, l0);
            split_pair(v.z, v.w, h1, l1);
            uint32_t off = (uint32_t)c * RB + (uint32_t)(q + 4 * j) * 8;
            STS64V2(xhb + off, h0, h1);
            STS64V2(xlb + off, l0, l1);
        }
        __syncthreads();

        if (t + 1 < T2A) {
            const float4* src = (const float4*)(xb + (size_t)c * MDIM + mg0 + 64);
#pragma unroll
            for (int j = 0; j < 4; ++j) stage[j] = src[q + 4 * j];
        }

        float D[4][4] = {};
#pragma unroll
        for (int kc = 0; kc < 4; ++kc) {
            const uint32_t kb = (uint32_t)(kc * 16) * RB;
            uint32_t bh0[4], bh1[4], bl0[4], bl1[4];
            ldm_x4t(bh0, xhb + boff + kb);
            ldm_x4t(bh1, xhb + boff + kb + 32);
            ldm_x4t(bl0, xlb + boff + kb);
            ldm_x4t(bl1, xlb + boff + kb + 32);
            mma16816(D[0], wah[kc], bh0[0], bh0[1]);
            mma16816(D[0], wah[kc], bl0[0], bl0[1]);
            mma16816(D[0], wal[kc], bh0[0], bh0[1]);
            mma16816(D[1], wah[kc], bh0[2], bh0[3]);
            mma16816(D[1], wah[kc], bl0[2], bl0[3]);
            mma16816(D[1], wal[kc], bh0[2], bh0[3]);
            mma16816(D[2], wah[kc], bh1[0], bh1[1]);
            mma16816(D[2], wah[kc], bl1[0], bl1[1]);
            mma16816(D[2], wal[kc], bh1[0], bh1[1]);
            mma16816(D[3], wah[kc], bh1[2], bh1[3]);
            mma16816(D[3], wah[kc], bl1[2], bl1[3]);
            mma16816(D[3], wal[kc], bh1[2], bh1[3]);
        }

        const int row = r0 + (lane >> 2);
        const int mg = mg0 + m0 + (lane & 3) * 2;
#pragma unroll
        for (int nb = 0; nb < 4; ++nb) {
            *(float2*)(zb + (size_t)row * MDIM + mg + nb * 8)       = make_float2(D[nb][0], D[nb][1]);
            *(float2*)(zb + (size_t)(row + 8) * MDIM + mg + nb * 8) = make_float2(D[nb][2], D[nb][3]);
        }
        __syncthreads();
    }
}

extern "C" void kernel_launch(void* const* d_in, const int* in_sizes, int n_in,
                              void* d_out, int out_size)
{
    const float* x = (const float*)d_in[0];
    float* z = (float*)d_out;

    gram_kernel<<<dim3(BATCH, S1G), NT>>>(x);
    chol_kernel<<<BATCH, NT>>>();
    apply_kernel<<<dim3(BATCH, S2A), NT>>>(x, z);
}